// round 9
// baseline (speedup 1.0000x reference)
#include <cuda_runtime.h>
#include <cuda_bf16.h>
#include <cstddef>
#include <cstdint>

// Two-layer LSTM recurrence, persistent kernel, TENSOR-CORE layer-1 GEMV.
// R9 = R8 algorithm (split-bf16 mma.m16n8k16, gate-interleaved N, shuffle
// gate exchange, fp32 pointwise) spread over 25 compute warps (2 n-tiles
// each) instead of 10 (5 each) -> 6.5 warps/SMSP for latency hiding.
//
// 128 blocks x 832 threads:
//   warps 0-24 : compute. warp w owns n-tiles 2w, 2w+1 (units 4w..4w+3),
//                both m-tiles (batch rows 0-31).
//   warp 25    : layer-2 (lane = batch elem), one step behind; stages x.

#define CELL     100
#define NB       32
#define THREADS  832
#define L2BASE   800
#define KPAD     112      // K padded to 7 k-tiles of 16
#define NKT      21       // 3 passes x 7 k-tiles
#define ASTRIDE  232      // bf16 per A row (hi 0-111, pad, lo 120-231); 464B
#define ALO      120      // col offset of h_lo region (16B aligned)
#define WSTR     120      // bf16 per W row; 240B
#define CSTRIDE  33       // c1sh row stride (floats)

#define LDSM_X4(r0,r1,r2,r3, addr) \
  asm volatile("ldmatrix.sync.aligned.m8n8.x4.shared.b16 {%0,%1,%2,%3}, [%4];" \
    : "=r"(r0), "=r"(r1), "=r"(r2), "=r"(r3) : "r"(addr))
#define LDSM_X2(r0,r1, addr) \
  asm volatile("ldmatrix.sync.aligned.m8n8.x2.shared.b16 {%0,%1}, [%2];" \
    : "=r"(r0), "=r"(r1) : "r"(addr))
#define MMA16816(d, a0,a1,a2,a3, b0,b1) \
  asm volatile("mma.sync.aligned.m16n8k16.row.col.f32.bf16.bf16.f32 " \
    "{%0,%1,%2,%3}, {%4,%5,%6,%7}, {%8,%9}, {%0,%1,%2,%3};" \
    : "+f"((d)[0]), "+f"((d)[1]), "+f"((d)[2]), "+f"((d)[3]) \
    : "r"(a0), "r"(a1), "r"(a2), "r"(a3), "r"(b0), "r"(b1))

__device__ __forceinline__ float sigm(float x) {
    return 1.0f / (1.0f + __expf(-x));
}
__device__ __forceinline__ float tanh_f(float x) {
    float e = __expf(2.0f * x);
    return 1.0f - 2.0f / (e + 1.0f);
}
__device__ __forceinline__ uint32_t smem_u32(const void* p) {
    return (uint32_t)__cvta_generic_to_shared(p);
}

__global__ void __launch_bounds__(THREADS, 1)
tsrnn_kernel(const float* __restrict__ input,
             const float* __restrict__ W_ih1, const float* __restrict__ W_hh1,
             const float* __restrict__ b_ih1, const float* __restrict__ b_hh1,
             const float* __restrict__ W_ih2, const float* __restrict__ W_hh2,
             const float* __restrict__ b_ih2, const float* __restrict__ b_hh2,
             float* __restrict__ out, int T, int FUT, int Btot)
{
    extern __shared__ char smem[];
    __nv_bfloat16* Whi = (__nv_bfloat16*)smem;          // [400][120] row n = 4u+k
    __nv_bfloat16* Wlo = Whi + 400 * WSTR;              // [400][120]
    __nv_bfloat16* Ash = Wlo + 400 * WSTR;              // [32][232]: hhi | pad | hlo
    float* c1sh   = (float*)(Ash + 32 * ASTRIDE);       // [100][33]
    float* w2i    = c1sh + CELL * CSTRIDE;              // [100][4]
    float* wih_sh = w2i + 400;                          // [100][4]
    float* bsum_sh= wih_sh + 400;                       // [100][4]
    float* xsh    = bsum_sh + 400;                      // [32]

    const int tid    = threadIdx.x;
    const int bglob0 = blockIdx.x * NB;
    const int wid    = tid >> 5;
    const int lane   = tid & 31;

    // ================= staging =================
    for (int idx = tid; idx < 400 * KPAD; idx += THREADS) {
        int n = idx / KPAD, kk = idx - n * KPAD;
        int u = n >> 2, k = n & 3;
        float w = (kk < CELL) ? W_hh1[(k * CELL + u) * CELL + kk] : 0.0f;
        __nv_bfloat16 hi = __float2bfloat16(w);
        Whi[n * WSTR + kk] = hi;
        Wlo[n * WSTR + kk] = __float2bfloat16(w - __bfloat162float(hi));
    }
    for (int idx = tid; idx < 32 * ASTRIDE; idx += THREADS)
        Ash[idx] = __float2bfloat16(0.0f);
    for (int idx = tid; idx < CELL * CSTRIDE; idx += THREADS) c1sh[idx] = 0.0f;
    for (int idx = tid; idx < 400; idx += THREADS) {
        int u = idx >> 2, k = idx & 3;
        w2i[idx]    = W_ih2[k * CELL + u];
        wih_sh[idx] = W_ih1[k * CELL + u];
        bsum_sh[idx]= b_ih1[k * CELL + u] + b_hh1[k * CELL + u];
    }
    if (tid < NB) xsh[tid] = 0.0f;

    // ================= per-thread setup =================
    const bool cw = (wid < 25);                 // compute warp
    const bool l2 = (tid >= L2BASE);            // warp 25
    const int  q  = lane & 3;
    const int  pp = q & 1;                      // 0: holds (i,f); 1: holds (g,o)
    const int  rowbase = lane >> 2;

    // ldmatrix lane addresses (byte offsets precomputed)
    const uint32_t Au32  = smem_u32(Ash);
    const uint32_t Whi32 = smem_u32(Whi);
    const uint32_t WLO_OFF = (uint32_t)(400 * WSTR * 2); // Wlo - Whi in bytes
    uint32_t aaddr[2], baddr[2];
    if (cw) {
        #pragma unroll
        for (int mt = 0; mt < 2; mt++)
            aaddr[mt] = Au32 + ((mt * 16 + (lane & 15)) * ASTRIDE + (lane >> 4) * 8) * 2;
        const int l4 = lane & 15;
        #pragma unroll
        for (int i = 0; i < 2; i++) {
            int nt = 2 * wid + i;
            baddr[i] = Whi32 + ((8 * nt + (l4 & 7)) * WSTR + ((l4 >> 3) & 1) * 8) * 2;
        }
    }

    // layer-2 per-lane constants + state
    const int bl2 = tid - L2BASE;
    float whh2[4], b2c[4];
    float h2 = 0.0f, c2 = 0.0f;
    if (l2) {
        #pragma unroll
        for (int k = 0; k < 4; k++) {
            whh2[k] = W_hh2[k];
            b2c[k]  = b_ih2[k] + b_hh2[k];
        }
    }

    float c1r[4];
    #pragma unroll
    for (int i = 0; i < 4; i++) c1r[i] = 0.0f;

    __syncthreads();

    // ================= main loop =================
    const int TOT = T + FUT;
    for (int t = 0; t < TOT; ++t) {
        float d[2][2][4];

        if (cw) {
            // ---- phase 1: GEMM on h[t-1] (split bf16, 21 k-tiles) ----
            #pragma unroll
            for (int mt = 0; mt < 2; mt++)
                #pragma unroll
                for (int i = 0; i < 2; i++)
                    #pragma unroll
                    for (int r = 0; r < 4; r++) d[mt][i][r] = 0.0f;

            #pragma unroll
            for (int kt = 0; kt < NKT; kt++) {
                const int p  = kt / 7;            // 0: hi*Whi, 1: lo*Whi, 2: hi*Wlo
                const int kk = kt - p * 7;
                const uint32_t acolb = (uint32_t)((kk * 16 + (p == 1 ? ALO : 0)) * 2);
                const uint32_t bcolb = (uint32_t)(kk * 32) + (p == 2 ? WLO_OFF : 0u);

                uint32_t a0[4], a1[4];
                LDSM_X4(a0[0], a0[1], a0[2], a0[3], aaddr[0] + acolb);
                LDSM_X4(a1[0], a1[1], a1[2], a1[3], aaddr[1] + acolb);
                #pragma unroll
                for (int i = 0; i < 2; i++) {
                    uint32_t b0, b1;
                    LDSM_X2(b0, b1, baddr[i] + bcolb);
                    MMA16816(d[0][i], a0[0], a0[1], a0[2], a0[3], b0, b1);
                    MMA16816(d[1][i], a1[0], a1[1], a1[2], a1[3], b0, b1);
                }
            }
        } else {
            // ---- layer-2 for step t-1, and x staging for step t ----
            if (t < T) {
                xsh[bl2] = input[(size_t)t * Btot + bglob0 + bl2];
            }
            if (t > 0) {
                const int tt = t - 1;
                const float* cp = c1sh + bl2;
                float di = 0.f, df = 0.f, dg = 0.f, dz = 0.f;
                #pragma unroll 10
                for (int uu = 0; uu < CELL; uu++) {
                    float cv  = cp[uu * CSTRIDE];
                    float4 w4 = *(const float4*)(w2i + uu * 4);
                    di = fmaf(cv, w4.x, di);
                    df = fmaf(cv, w4.y, df);
                    dg = fmaf(cv, w4.z, dg);
                    dz = fmaf(cv, w4.w, dz);
                }
                float pi = fmaf(h2, whh2[0], di + b2c[0]);
                float pf = fmaf(h2, whh2[1], df + b2c[1]);
                float pg = fmaf(h2, whh2[2], dg + b2c[2]);
                float po = fmaf(h2, whh2[3], dz + b2c[3]);
                float c  = sigm(pf) * c2 + sigm(pi) * tanh_f(pg);
                c2 = c;
                h2 = sigm(po) * tanh_f(c);
                if (t >= T) xsh[bl2] = c;               // x for future step t
                if (tt >= T) out[(size_t)(bglob0 + bl2) * FUT + (tt - T)] = c;
            }
        }

        __syncthreads();   // D ready (regs); A/c1 reads done; xsh holds x(t)

        if (cw) {
            // ---- phase 2: epilogue (gates -> cell -> h split -> stores) ----
            #pragma unroll
            for (int mt = 0; mt < 2; mt++) {
                #pragma unroll
                for (int i = 0; i < 2; i++) {
                    const int u = 4 * wid + 2 * i + (q >> 1);
                    float* dd = d[mt][i];
                    // exchange with lane^1: even keeps row r, odd keeps row r+8
                    float g0 = pp ? dd[0] : dd[2];
                    float g1 = pp ? dd[1] : dd[3];
                    float r0 = __shfl_xor_sync(0xffffffffu, g0, 1);
                    float r1 = __shfl_xor_sync(0xffffffffu, g1, 1);
                    float gi, gf, gg, go;
                    if (!pp) { gi = dd[0]; gf = dd[1]; gg = r0;    go = r1;    }
                    else     { gi = r0;    gf = r1;    gg = dd[2]; go = dd[3]; }

                    const int row = mt * 16 + rowbase + (pp ? 8 : 0);
                    const float xv = xsh[row];
                    const float4 bs = *(const float4*)(bsum_sh + u * 4);
                    const float4 wi = *(const float4*)(wih_sh + u * 4);
                    float pi = fmaf(xv, wi.x, gi + bs.x);
                    float pf = fmaf(xv, wi.y, gf + bs.y);
                    float pg = fmaf(xv, wi.z, gg + bs.z);
                    float po = fmaf(xv, wi.w, go + bs.w);
                    const int ci = mt * 2 + i;
                    float c = sigm(pf) * c1r[ci] + sigm(pi) * tanh_f(pg);
                    c1r[ci] = c;
                    float h = sigm(po) * tanh_f(c);

                    c1sh[u * CSTRIDE + row] = c;
                    __nv_bfloat16 hh = __float2bfloat16(h);
                    Ash[row * ASTRIDE + u]       = hh;
                    Ash[row * ASTRIDE + ALO + u] =
                        __float2bfloat16(h - __bfloat162float(hh));
                }
            }
        }

        __syncthreads();   // new A / c1 visible for next step
    }

    // drain: layer-2 for the final step TOT-1
    if (l2) {
        const int tt = TOT - 1;
        const float* cp = c1sh + bl2;
        float di = 0.f, df = 0.f, dg = 0.f, dz = 0.f;
        #pragma unroll 10
        for (int uu = 0; uu < CELL; uu++) {
            float cv  = cp[uu * CSTRIDE];
            float4 w4 = *(const float4*)(w2i + uu * 4);
            di = fmaf(cv, w4.x, di);
            df = fmaf(cv, w4.y, df);
            dg = fmaf(cv, w4.z, dg);
            dz = fmaf(cv, w4.w, dz);
        }
        float pi = fmaf(h2, whh2[0], di + b2c[0]);
        float pf = fmaf(h2, whh2[1], df + b2c[1]);
        float pg = fmaf(h2, whh2[2], dg + b2c[2]);
        float po = fmaf(h2, whh2[3], dz + b2c[3]);
        float c  = sigm(pf) * c2 + sigm(pi) * tanh_f(pg);
        out[(size_t)(bglob0 + bl2) * FUT + (tt - T)] = c;
    }
}

extern "C" void kernel_launch(void* const* d_in, const int* in_sizes, int n_in,
                              void* d_out, int out_size)
{
    const float* input = (const float*)d_in[0];
    const float* W_ih1 = (const float*)d_in[1];
    const float* W_hh1 = (const float*)d_in[2];
    const float* b_ih1 = (const float*)d_in[3];
    const float* b_hh1 = (const float*)d_in[4];
    const float* W_ih2 = (const float*)d_in[5];
    const float* W_hh2 = (const float*)d_in[6];
    const float* b_ih2 = (const float*)d_in[7];
    const float* b_hh2 = (const float*)d_in[8];
    float* out = (float*)d_out;

    const int Btot = 4096;
    const int T    = in_sizes[0] / Btot;   // 512
    const int FUT  = out_size   / Btot;    // 64

    const int smem = 400 * WSTR * 2 * 2      // Whi + Wlo      192,000 B
                   + 32 * ASTRIDE * 2        // Ash             14,848 B
                   + (CELL * CSTRIDE         // c1sh             3,300 f
                      + 400 + 400 + 400      // w2i, wih, bsum   1,200 f
                      + NB) * 4;             // xsh                 32 f
                                             // total ~224,976 B

    cudaFuncSetAttribute(tsrnn_kernel,
                         cudaFuncAttributeMaxDynamicSharedMemorySize, smem);

    tsrnn_kernel<<<Btot / NB, THREADS, smem>>>(
        input, W_ih1, W_hh1, b_ih1, b_hh1,
        W_ih2, W_hh2, b_ih2, b_hh2,
        out, T, FUT, Btot);
}

// round 10
// speedup vs baseline: 1.6185x; 1.6185x over previous
#include <cuda_runtime.h>
#include <cuda_bf16.h>
#include <cstddef>
#include <cstdint>

// Two-layer LSTM recurrence, persistent kernel, TENSOR-CORE layer-1 GEMV.
// R10 = R8 (best measured: 10 compute warps x 2 m-tiles x 5 n-tiles,
// split-bf16 mma.m16n8k16, fp32 pointwise) with the fp32 DIVISIONS in
// sigmoid/tanh replaced by single-instruction rcp.approx (the hidden
// ~75-instruction-per-unit Newton-refined division was the top issue load).
//
// 128 blocks x 352 threads:
//   warps 0-9 : compute. warp w owns n-tiles 5w..5w+4 (units 10w..10w+9),
//               both m-tiles (batch rows 0-31).
//   warp 10   : layer-2 (lane = batch elem), one step behind; stages x.

#define CELL     100
#define NB       32
#define THREADS  352
#define L2BASE   320
#define KPAD     112      // K padded to 7 k-tiles of 16
#define NKT      21       // 3 passes x 7 k-tiles
#define ASTRIDE  232      // bf16 per A row (hi 0-111, pad, lo 120-231); 464B
#define ALO      120      // col offset of h_lo region (16B aligned)
#define WSTR     120      // bf16 per W row; 240B
#define CSTRIDE  33       // c1sh row stride (floats)

#define LDSM_X4(r0,r1,r2,r3, addr) \
  asm volatile("ldmatrix.sync.aligned.m8n8.x4.shared.b16 {%0,%1,%2,%3}, [%4];" \
    : "=r"(r0), "=r"(r1), "=r"(r2), "=r"(r3) : "r"(addr))
#define LDSM_X2(r0,r1, addr) \
  asm volatile("ldmatrix.sync.aligned.m8n8.x2.shared.b16 {%0,%1}, [%2];" \
    : "=r"(r0), "=r"(r1) : "r"(addr))
#define MMA16816(d, a0,a1,a2,a3, b0,b1) \
  asm volatile("mma.sync.aligned.m16n8k16.row.col.f32.bf16.bf16.f32 " \
    "{%0,%1,%2,%3}, {%4,%5,%6,%7}, {%8,%9}, {%0,%1,%2,%3};" \
    : "+f"((d)[0]), "+f"((d)[1]), "+f"((d)[2]), "+f"((d)[3]) \
    : "r"(a0), "r"(a1), "r"(a2), "r"(a3), "r"(b0), "r"(b1))

__device__ __forceinline__ float rcp_approx(float x) {
    float r;
    asm("rcp.approx.f32 %0, %1;" : "=f"(r) : "f"(x));
    return r;
}
__device__ __forceinline__ float sigm(float x) {
    // 1/(1+exp(-x)) with single-MUFU reciprocal (rel err ~2^-22.5)
    return rcp_approx(1.0f + __expf(-x));
}
__device__ __forceinline__ float tanh_f(float x) {
    // tanh(x) = 1 - 2/(exp(2x)+1); correct limits with __expf
    float e = __expf(2.0f * x);
    return fmaf(-2.0f, rcp_approx(e + 1.0f), 1.0f);
}
__device__ __forceinline__ uint32_t smem_u32(const void* p) {
    return (uint32_t)__cvta_generic_to_shared(p);
}

__global__ void __launch_bounds__(THREADS, 1)
tsrnn_kernel(const float* __restrict__ input,
             const float* __restrict__ W_ih1, const float* __restrict__ W_hh1,
             const float* __restrict__ b_ih1, const float* __restrict__ b_hh1,
             const float* __restrict__ W_ih2, const float* __restrict__ W_hh2,
             const float* __restrict__ b_ih2, const float* __restrict__ b_hh2,
             float* __restrict__ out, int T, int FUT, int Btot)
{
    extern __shared__ char smem[];
    __nv_bfloat16* Whi = (__nv_bfloat16*)smem;          // [400][120] row n = 4u+k
    __nv_bfloat16* Wlo = Whi + 400 * WSTR;              // [400][120]
    __nv_bfloat16* Ash = Wlo + 400 * WSTR;              // [32][232]: hhi | pad | hlo
    float* c1sh   = (float*)(Ash + 32 * ASTRIDE);       // [100][33]
    float* w2i    = c1sh + CELL * CSTRIDE;              // [100][4]
    float* wih_sh = w2i + 400;                          // [100][4]
    float* bsum_sh= wih_sh + 400;                       // [100][4]
    float* xsh    = bsum_sh + 400;                      // [32]

    const int tid    = threadIdx.x;
    const int bglob0 = blockIdx.x * NB;
    const int wid    = tid >> 5;
    const int lane   = tid & 31;

    // ================= staging =================
    for (int idx = tid; idx < 400 * KPAD; idx += THREADS) {
        int n = idx / KPAD, kk = idx - n * KPAD;
        int u = n >> 2, k = n & 3;
        float w = (kk < CELL) ? W_hh1[(k * CELL + u) * CELL + kk] : 0.0f;
        __nv_bfloat16 hi = __float2bfloat16(w);
        Whi[n * WSTR + kk] = hi;
        Wlo[n * WSTR + kk] = __float2bfloat16(w - __bfloat162float(hi));
    }
    for (int idx = tid; idx < 32 * ASTRIDE; idx += THREADS)
        Ash[idx] = __float2bfloat16(0.0f);
    for (int idx = tid; idx < CELL * CSTRIDE; idx += THREADS) c1sh[idx] = 0.0f;
    for (int idx = tid; idx < 400; idx += THREADS) {
        int u = idx >> 2, k = idx & 3;
        w2i[idx]    = W_ih2[k * CELL + u];
        wih_sh[idx] = W_ih1[k * CELL + u];
        bsum_sh[idx]= b_ih1[k * CELL + u] + b_hh1[k * CELL + u];
    }
    if (tid < NB) xsh[tid] = 0.0f;

    // ================= per-thread setup =================
    const bool cw = (wid < 10);                 // compute warp
    const bool l2 = (tid >= L2BASE) && (tid < L2BASE + NB);
    const int  q  = lane & 3;
    const int  pp = q & 1;                      // 0: holds (i,f); 1: holds (g,o)
    const int  rowbase = lane >> 2;

    // ldmatrix lane addresses (byte offsets precomputed)
    const uint32_t Au32  = smem_u32(Ash);
    const uint32_t Whi32 = smem_u32(Whi);
    const uint32_t WLO_OFF = (uint32_t)(400 * WSTR * 2); // Wlo - Whi in bytes
    uint32_t aaddr[2], baddr[5];
    if (cw) {
        #pragma unroll
        for (int mt = 0; mt < 2; mt++)
            aaddr[mt] = Au32 + ((mt * 16 + (lane & 15)) * ASTRIDE + (lane >> 4) * 8) * 2;
        const int l4 = lane & 15;
        #pragma unroll
        for (int i = 0; i < 5; i++) {
            int nt = 5 * wid + i;
            baddr[i] = Whi32 + ((8 * nt + (l4 & 7)) * WSTR + ((l4 >> 3) & 1) * 8) * 2;
        }
    }

    // layer-2 per-lane constants + state
    const int bl2 = tid - L2BASE;
    float whh2[4], b2c[4];
    float h2 = 0.0f, c2 = 0.0f;
    if (l2) {
        #pragma unroll
        for (int k = 0; k < 4; k++) {
            whh2[k] = W_hh2[k];
            b2c[k]  = b_ih2[k] + b_hh2[k];
        }
    }

    float c1r[10];
    #pragma unroll
    for (int i = 0; i < 10; i++) c1r[i] = 0.0f;

    __syncthreads();

    // ================= main loop =================
    const int TOT = T + FUT;
    for (int t = 0; t < TOT; ++t) {
        float d[2][5][4];

        if (cw) {
            // ---- phase 1: GEMM on h[t-1] (split bf16, 21 k-tiles) ----
            #pragma unroll
            for (int mt = 0; mt < 2; mt++)
                #pragma unroll
                for (int i = 0; i < 5; i++)
                    #pragma unroll
                    for (int r = 0; r < 4; r++) d[mt][i][r] = 0.0f;

            #pragma unroll
            for (int kt = 0; kt < NKT; kt++) {
                const int p  = kt / 7;            // 0: hi*Whi, 1: lo*Whi, 2: hi*Wlo
                const int kk = kt - p * 7;
                const uint32_t acolb = (uint32_t)((kk * 16 + (p == 1 ? ALO : 0)) * 2);
                const uint32_t bcolb = (uint32_t)(kk * 32) + (p == 2 ? WLO_OFF : 0u);

                uint32_t a0[4], a1[4];
                LDSM_X4(a0[0], a0[1], a0[2], a0[3], aaddr[0] + acolb);
                LDSM_X4(a1[0], a1[1], a1[2], a1[3], aaddr[1] + acolb);
                #pragma unroll
                for (int i = 0; i < 5; i++) {
                    uint32_t b0, b1;
                    LDSM_X2(b0, b1, baddr[i] + bcolb);
                    MMA16816(d[0][i], a0[0], a0[1], a0[2], a0[3], b0, b1);
                    MMA16816(d[1][i], a1[0], a1[1], a1[2], a1[3], b0, b1);
                }
            }
        } else if (l2) {
            // ---- layer-2 for step t-1, and x staging for step t ----
            if (t < T) {
                xsh[bl2] = input[(size_t)t * Btot + bglob0 + bl2];
            }
            if (t > 0) {
                const int tt = t - 1;
                const float* cp = c1sh + bl2;
                float di = 0.f, df = 0.f, dg = 0.f, dz = 0.f;
                #pragma unroll 10
                for (int uu = 0; uu < CELL; uu++) {
                    float cv  = cp[uu * CSTRIDE];
                    float4 w4 = *(const float4*)(w2i + uu * 4);
                    di = fmaf(cv, w4.x, di);
                    df = fmaf(cv, w4.y, df);
                    dg = fmaf(cv, w4.z, dg);
                    dz = fmaf(cv, w4.w, dz);
                }
                float pi = fmaf(h2, whh2[0], di + b2c[0]);
                float pf = fmaf(h2, whh2[1], df + b2c[1]);
                float pg = fmaf(h2, whh2[2], dg + b2c[2]);
                float po = fmaf(h2, whh2[3], dz + b2c[3]);
                float c  = sigm(pf) * c2 + sigm(pi) * tanh_f(pg);
                c2 = c;
                h2 = sigm(po) * tanh_f(c);
                if (t >= T) xsh[bl2] = c;               // x for future step t
                if (tt >= T) out[(size_t)(bglob0 + bl2) * FUT + (tt - T)] = c;
            }
        }

        __syncthreads();   // D ready (regs); A/c1 reads done; xsh holds x(t)

        if (cw) {
            // ---- phase 2: epilogue (gates -> cell -> h split -> stores) ----
            #pragma unroll
            for (int mt = 0; mt < 2; mt++) {
                #pragma unroll
                for (int i = 0; i < 5; i++) {
                    const int u = 2 * (5 * wid + i) + (q >> 1);
                    float* dd = d[mt][i];
                    // exchange with lane^1: even keeps row r, odd keeps row r+8
                    float g0 = pp ? dd[0] : dd[2];
                    float g1 = pp ? dd[1] : dd[3];
                    float r0 = __shfl_xor_sync(0xffffffffu, g0, 1);
                    float r1 = __shfl_xor_sync(0xffffffffu, g1, 1);
                    float gi, gf, gg, go;
                    if (!pp) { gi = dd[0]; gf = dd[1]; gg = r0;    go = r1;    }
                    else     { gi = r0;    gf = r1;    gg = dd[2]; go = dd[3]; }

                    const int row = mt * 16 + rowbase + (pp ? 8 : 0);
                    const float xv = xsh[row];
                    const float4 bs = *(const float4*)(bsum_sh + u * 4);
                    const float4 wi = *(const float4*)(wih_sh + u * 4);
                    float pi = fmaf(xv, wi.x, gi + bs.x);
                    float pf = fmaf(xv, wi.y, gf + bs.y);
                    float pg = fmaf(xv, wi.z, gg + bs.z);
                    float po = fmaf(xv, wi.w, go + bs.w);
                    const int ci = mt * 5 + i;
                    float c = sigm(pf) * c1r[ci] + sigm(pi) * tanh_f(pg);
                    c1r[ci] = c;
                    float h = sigm(po) * tanh_f(c);

                    c1sh[u * CSTRIDE + row] = c;
                    __nv_bfloat16 hh = __float2bfloat16(h);
                    Ash[row * ASTRIDE + u]       = hh;
                    Ash[row * ASTRIDE + ALO + u] =
                        __float2bfloat16(h - __bfloat162float(hh));
                }
            }
        }

        __syncthreads();   // new A / c1 visible for next step
    }

    // drain: layer-2 for the final step TOT-1
    if (l2) {
        const int tt = TOT - 1;
        const float* cp = c1sh + bl2;
        float di = 0.f, df = 0.f, dg = 0.f, dz = 0.f;
        #pragma unroll 10
        for (int uu = 0; uu < CELL; uu++) {
            float cv  = cp[uu * CSTRIDE];
            float4 w4 = *(const float4*)(w2i + uu * 4);
            di = fmaf(cv, w4.x, di);
            df = fmaf(cv, w4.y, df);
            dg = fmaf(cv, w4.z, dg);
            dz = fmaf(cv, w4.w, dz);
        }
        float pi = fmaf(h2, whh2[0], di + b2c[0]);
        float pf = fmaf(h2, whh2[1], df + b2c[1]);
        float pg = fmaf(h2, whh2[2], dg + b2c[2]);
        float po = fmaf(h2, whh2[3], dz + b2c[3]);
        float c  = sigm(pf) * c2 + sigm(pi) * tanh_f(pg);
        out[(size_t)(bglob0 + bl2) * FUT + (tt - T)] = c;
    }
}

extern "C" void kernel_launch(void* const* d_in, const int* in_sizes, int n_in,
                              void* d_out, int out_size)
{
    const float* input = (const float*)d_in[0];
    const float* W_ih1 = (const float*)d_in[1];
    const float* W_hh1 = (const float*)d_in[2];
    const float* b_ih1 = (const float*)d_in[3];
    const float* b_hh1 = (const float*)d_in[4];
    const float* W_ih2 = (const float*)d_in[5];
    const float* W_hh2 = (const float*)d_in[6];
    const float* b_ih2 = (const float*)d_in[7];
    const float* b_hh2 = (const float*)d_in[8];
    float* out = (float*)d_out;

    const int Btot = 4096;
    const int T    = in_sizes[0] / Btot;   // 512
    const int FUT  = out_size   / Btot;    // 64

    const int smem = 400 * WSTR * 2 * 2      // Whi + Wlo      192,000 B
                   + 32 * ASTRIDE * 2        // Ash             14,848 B
                   + (CELL * CSTRIDE         // c1sh             3,300 f
                      + 400 + 400 + 400      // w2i, wih, bsum   1,200 f
                      + NB) * 4;             // xsh                 32 f
                                             // total ~224,976 B

    cudaFuncSetAttribute(tsrnn_kernel,
                         cudaFuncAttributeMaxDynamicSharedMemorySize, smem);

    tsrnn_kernel<<<Btot / NB, THREADS, smem>>>(
        input, W_ih1, W_hh1, b_ih1, b_hh1,
        W_ih2, W_hh2, b_ih2, b_hh2,
        out, T, FUT, Btot);
}

// round 11
// speedup vs baseline: 1.9121x; 1.1814x over previous
#include <cuda_runtime.h>
#include <cuda_bf16.h>
#include <cstddef>
#include <cstdint>

// Two-layer LSTM recurrence, persistent kernel, TENSOR-CORE layer-1 GEMV.
// R11 = R10 (10 compute warps x 2 m-tiles x 5 n-tiles, split-bf16
// mma.m16n8k16, fp32 pointwise) with:
//   - tanh.approx.f32 HW activations in the compute-warp epilogue
//     (sigmoid = 0.5 + 0.5*tanh(x/2)): 5 MUFU/cell instead of 10.
//   - x fetched by compute warps via LDG issued before the GEMM
//     (observed phase); xsh only carries c2 feedback in the future phase.
// Layer-2 warp keeps exact EX2+RCP activations (its output is the answer).

#define CELL     100
#define NB       32
#define THREADS  352
#define L2BASE   320
#define KPAD     112      // K padded to 7 k-tiles of 16
#define NKT      21       // 3 passes x 7 k-tiles
#define ASTRIDE  232      // bf16 per A row (hi 0-111, pad, lo 120-231); 464B
#define ALO      120      // col offset of h_lo region (16B aligned)
#define WSTR     120      // bf16 per W row; 240B
#define CSTRIDE  33       // c1sh row stride (floats)

#define LDSM_X4(r0,r1,r2,r3, addr) \
  asm volatile("ldmatrix.sync.aligned.m8n8.x4.shared.b16 {%0,%1,%2,%3}, [%4];" \
    : "=r"(r0), "=r"(r1), "=r"(r2), "=r"(r3) : "r"(addr))
#define LDSM_X2(r0,r1, addr) \
  asm volatile("ldmatrix.sync.aligned.m8n8.x2.shared.b16 {%0,%1}, [%2];" \
    : "=r"(r0), "=r"(r1) : "r"(addr))
#define MMA16816(d, a0,a1,a2,a3, b0,b1) \
  asm volatile("mma.sync.aligned.m16n8k16.row.col.f32.bf16.bf16.f32 " \
    "{%0,%1,%2,%3}, {%4,%5,%6,%7}, {%8,%9}, {%0,%1,%2,%3};" \
    : "+f"((d)[0]), "+f"((d)[1]), "+f"((d)[2]), "+f"((d)[3]) \
    : "r"(a0), "r"(a1), "r"(a2), "r"(a3), "r"(b0), "r"(b1))

__device__ __forceinline__ float rcp_approx(float x) {
    float r;
    asm("rcp.approx.f32 %0, %1;" : "=f"(r) : "f"(x));
    return r;
}
// ---- fast path (compute warps): single-MUFU HW tanh ----
__device__ __forceinline__ float tanh_hw(float x) {
    float r;
    asm("tanh.approx.f32 %0, %1;" : "=f"(r) : "f"(x));
    return r;
}
__device__ __forceinline__ float sigm_fast(float x) {
    return fmaf(0.5f, tanh_hw(0.5f * x), 0.5f);
}
// ---- exact path (layer-2 warp) ----
__device__ __forceinline__ float sigm(float x) {
    return rcp_approx(1.0f + __expf(-x));
}
__device__ __forceinline__ float tanh_f(float x) {
    float e = __expf(2.0f * x);
    return fmaf(-2.0f, rcp_approx(e + 1.0f), 1.0f);
}
__device__ __forceinline__ uint32_t smem_u32(const void* p) {
    return (uint32_t)__cvta_generic_to_shared(p);
}

__global__ void __launch_bounds__(THREADS, 1)
tsrnn_kernel(const float* __restrict__ input,
             const float* __restrict__ W_ih1, const float* __restrict__ W_hh1,
             const float* __restrict__ b_ih1, const float* __restrict__ b_hh1,
             const float* __restrict__ W_ih2, const float* __restrict__ W_hh2,
             const float* __restrict__ b_ih2, const float* __restrict__ b_hh2,
             float* __restrict__ out, int T, int FUT, int Btot)
{
    extern __shared__ char smem[];
    __nv_bfloat16* Whi = (__nv_bfloat16*)smem;          // [400][120] row n = 4u+k
    __nv_bfloat16* Wlo = Whi + 400 * WSTR;              // [400][120]
    __nv_bfloat16* Ash = Wlo + 400 * WSTR;              // [32][232]: hhi | pad | hlo
    float* c1sh   = (float*)(Ash + 32 * ASTRIDE);       // [100][33]
    float* w2i    = c1sh + CELL * CSTRIDE;              // [100][4]
    float* wih_sh = w2i + 400;                          // [100][4]
    float* bsum_sh= wih_sh + 400;                       // [100][4]
    float* xsh    = bsum_sh + 400;                      // [32] (future phase)

    const int tid    = threadIdx.x;
    const int bglob0 = blockIdx.x * NB;
    const int wid    = tid >> 5;
    const int lane   = tid & 31;

    // ================= staging =================
    for (int idx = tid; idx < 400 * KPAD; idx += THREADS) {
        int n = idx / KPAD, kk = idx - n * KPAD;
        int u = n >> 2, k = n & 3;
        float w = (kk < CELL) ? W_hh1[(k * CELL + u) * CELL + kk] : 0.0f;
        __nv_bfloat16 hi = __float2bfloat16(w);
        Whi[n * WSTR + kk] = hi;
        Wlo[n * WSTR + kk] = __float2bfloat16(w - __bfloat162float(hi));
    }
    for (int idx = tid; idx < 32 * ASTRIDE; idx += THREADS)
        Ash[idx] = __float2bfloat16(0.0f);
    for (int idx = tid; idx < CELL * CSTRIDE; idx += THREADS) c1sh[idx] = 0.0f;
    for (int idx = tid; idx < 400; idx += THREADS) {
        int u = idx >> 2, k = idx & 3;
        w2i[idx]    = W_ih2[k * CELL + u];
        wih_sh[idx] = W_ih1[k * CELL + u];
        bsum_sh[idx]= b_ih1[k * CELL + u] + b_hh1[k * CELL + u];
    }
    if (tid < NB) xsh[tid] = 0.0f;

    // ================= per-thread setup =================
    const bool cw = (wid < 10);                 // compute warp
    const bool l2 = (tid >= L2BASE) && (tid < L2BASE + NB);
    const int  q  = lane & 3;
    const int  pp = q & 1;                      // 0: holds (i,f); 1: holds (g,o)
    const int  rowbase = lane >> 2;
    const int  row0 = rowbase + (pp ? 8 : 0);   // m-tile 0 row
    const int  row1 = row0 + 16;                // m-tile 1 row

    // ldmatrix lane addresses (byte offsets precomputed)
    const uint32_t Au32  = smem_u32(Ash);
    const uint32_t Whi32 = smem_u32(Whi);
    const uint32_t WLO_OFF = (uint32_t)(400 * WSTR * 2); // Wlo - Whi in bytes
    uint32_t aaddr[2], baddr[5];
    if (cw) {
        #pragma unroll
        for (int mt = 0; mt < 2; mt++)
            aaddr[mt] = Au32 + ((mt * 16 + (lane & 15)) * ASTRIDE + (lane >> 4) * 8) * 2;
        const int l4 = lane & 15;
        #pragma unroll
        for (int i = 0; i < 5; i++) {
            int nt = 5 * wid + i;
            baddr[i] = Whi32 + ((8 * nt + (l4 & 7)) * WSTR + ((l4 >> 3) & 1) * 8) * 2;
        }
    }

    // layer-2 per-lane constants + state
    const int bl2 = tid - L2BASE;
    float whh2[4], b2c[4];
    float h2 = 0.0f, c2 = 0.0f;
    if (l2) {
        #pragma unroll
        for (int k = 0; k < 4; k++) {
            whh2[k] = W_hh2[k];
            b2c[k]  = b_ih2[k] + b_hh2[k];
        }
    }

    float c1r[10];
    #pragma unroll
    for (int i = 0; i < 10; i++) c1r[i] = 0.0f;

    __syncthreads();

    // ================= main loop =================
    const int TOT = T + FUT;
    for (int t = 0; t < TOT; ++t) {
        const bool fut = (t >= T);
        float d[2][5][4];
        float xv[2];

        if (cw) {
            // ---- x prefetch (observed): LDG issued before the GEMM ----
            if (!fut) {
                const float* xp = input + (size_t)t * Btot + bglob0;
                xv[0] = __ldg(xp + row0);
                xv[1] = __ldg(xp + row1);
            }

            // ---- phase 1: GEMM on h[t-1] (split bf16, 21 k-tiles) ----
            #pragma unroll
            for (int mt = 0; mt < 2; mt++)
                #pragma unroll
                for (int i = 0; i < 5; i++)
                    #pragma unroll
                    for (int r = 0; r < 4; r++) d[mt][i][r] = 0.0f;

            #pragma unroll
            for (int kt = 0; kt < NKT; kt++) {
                const int p  = kt / 7;            // 0: hi*Whi, 1: lo*Whi, 2: hi*Wlo
                const int kk = kt - p * 7;
                const uint32_t acolb = (uint32_t)((kk * 16 + (p == 1 ? ALO : 0)) * 2);
                const uint32_t bcolb = (uint32_t)(kk * 32) + (p == 2 ? WLO_OFF : 0u);

                uint32_t a0[4], a1[4];
                LDSM_X4(a0[0], a0[1], a0[2], a0[3], aaddr[0] + acolb);
                LDSM_X4(a1[0], a1[1], a1[2], a1[3], aaddr[1] + acolb);
                #pragma unroll
                for (int i = 0; i < 5; i++) {
                    uint32_t b0, b1;
                    LDSM_X2(b0, b1, baddr[i] + bcolb);
                    MMA16816(d[0][i], a0[0], a0[1], a0[2], a0[3], b0, b1);
                    MMA16816(d[1][i], a1[0], a1[1], a1[2], a1[3], b0, b1);
                }
            }
        } else if (l2) {
            // ---- layer-2 for step t-1 ----
            if (t > 0) {
                const int tt = t - 1;
                const float* cp = c1sh + bl2;
                float di = 0.f, df = 0.f, dg = 0.f, dz = 0.f;
                #pragma unroll 10
                for (int uu = 0; uu < CELL; uu++) {
                    float cv  = cp[uu * CSTRIDE];
                    float4 w4 = *(const float4*)(w2i + uu * 4);
                    di = fmaf(cv, w4.x, di);
                    df = fmaf(cv, w4.y, df);
                    dg = fmaf(cv, w4.z, dg);
                    dz = fmaf(cv, w4.w, dz);
                }
                float pi = fmaf(h2, whh2[0], di + b2c[0]);
                float pf = fmaf(h2, whh2[1], df + b2c[1]);
                float pg = fmaf(h2, whh2[2], dg + b2c[2]);
                float po = fmaf(h2, whh2[3], dz + b2c[3]);
                float c  = sigm(pf) * c2 + sigm(pi) * tanh_f(pg);
                c2 = c;
                h2 = sigm(po) * tanh_f(c);
                if (t >= T) xsh[bl2] = c;               // x for future step t
                if (tt >= T) out[(size_t)(bglob0 + bl2) * FUT + (tt - T)] = c;
            }
        }

        __syncthreads();   // D ready (regs); A/c1 reads done; xsh holds x(t)

        if (cw) {
            if (fut) {
                xv[0] = xsh[row0];
                xv[1] = xsh[row1];
            }
            // ---- phase 2: epilogue (gates -> cell -> h split -> stores) ----
            #pragma unroll
            for (int mt = 0; mt < 2; mt++) {
                #pragma unroll
                for (int i = 0; i < 5; i++) {
                    const int u = 2 * (5 * wid + i) + (q >> 1);
                    float* dd = d[mt][i];
                    // exchange with lane^1: even keeps row r, odd keeps row r+8
                    float g0 = pp ? dd[0] : dd[2];
                    float g1 = pp ? dd[1] : dd[3];
                    float r0 = __shfl_xor_sync(0xffffffffu, g0, 1);
                    float r1 = __shfl_xor_sync(0xffffffffu, g1, 1);
                    float gi, gf, gg, go;
                    if (!pp) { gi = dd[0]; gf = dd[1]; gg = r0;    go = r1;    }
                    else     { gi = r0;    gf = r1;    gg = dd[2]; go = dd[3]; }

                    const int row = mt * 16 + row0;
                    const float x = xv[mt];
                    const float4 bs = *(const float4*)(bsum_sh + u * 4);
                    const float4 wi = *(const float4*)(wih_sh + u * 4);
                    float pi = fmaf(x, wi.x, gi + bs.x);
                    float pf = fmaf(x, wi.y, gf + bs.y);
                    float pg = fmaf(x, wi.z, gg + bs.z);
                    float po = fmaf(x, wi.w, go + bs.w);
                    const int ci = mt * 5 + i;
                    float c = sigm_fast(pf) * c1r[ci] + sigm_fast(pi) * tanh_hw(pg);
                    c1r[ci] = c;
                    float h = sigm_fast(po) * tanh_hw(c);

                    c1sh[u * CSTRIDE + row] = c;
                    __nv_bfloat16 hh = __float2bfloat16(h);
                    Ash[row * ASTRIDE + u]       = hh;
                    Ash[row * ASTRIDE + ALO + u] =
                        __float2bfloat16(h - __bfloat162float(hh));
                }
            }
        }

        __syncthreads();   // new A / c1 visible for next step
    }

    // drain: layer-2 for the final step TOT-1
    if (l2) {
        const int tt = TOT - 1;
        const float* cp = c1sh + bl2;
        float di = 0.f, df = 0.f, dg = 0.f, dz = 0.f;
        #pragma unroll 10
        for (int uu = 0; uu < CELL; uu++) {
            float cv  = cp[uu * CSTRIDE];
            float4 w4 = *(const float4*)(w2i + uu * 4);
            di = fmaf(cv, w4.x, di);
            df = fmaf(cv, w4.y, df);
            dg = fmaf(cv, w4.z, dg);
            dz = fmaf(cv, w4.w, dz);
        }
        float pi = fmaf(h2, whh2[0], di + b2c[0]);
        float pf = fmaf(h2, whh2[1], df + b2c[1]);
        float pg = fmaf(h2, whh2[2], dg + b2c[2]);
        float po = fmaf(h2, whh2[3], dz + b2c[3]);
        float c  = sigm(pf) * c2 + sigm(pi) * tanh_f(pg);
        out[(size_t)(bglob0 + bl2) * FUT + (tt - T)] = c;
    }
}

extern "C" void kernel_launch(void* const* d_in, const int* in_sizes, int n_in,
                              void* d_out, int out_size)
{
    const float* input = (const float*)d_in[0];
    const float* W_ih1 = (const float*)d_in[1];
    const float* W_hh1 = (const float*)d_in[2];
    const float* b_ih1 = (const float*)d_in[3];
    const float* b_hh1 = (const float*)d_in[4];
    const float* W_ih2 = (const float*)d_in[5];
    const float* W_hh2 = (const float*)d_in[6];
    const float* b_ih2 = (const float*)d_in[7];
    const float* b_hh2 = (const float*)d_in[8];
    float* out = (float*)d_out;

    const int Btot = 4096;
    const int T    = in_sizes[0] / Btot;   // 512
    const int FUT  = out_size   / Btot;    // 64

    const int smem = 400 * WSTR * 2 * 2      // Whi + Wlo      192,000 B
                   + 32 * ASTRIDE * 2        // Ash             14,848 B
                   + (CELL * CSTRIDE         // c1sh             3,300 f
                      + 400 + 400 + 400      // w2i, wih, bsum   1,200 f
                      + NB) * 4;             // xsh                 32 f
                                             // total ~224,976 B

    cudaFuncSetAttribute(tsrnn_kernel,
                         cudaFuncAttributeMaxDynamicSharedMemorySize, smem);

    tsrnn_kernel<<<Btot / NB, THREADS, smem>>>(
        input, W_ih1, W_hh1, b_ih1, b_hh1,
        W_ih2, W_hh2, b_ih2, b_hh2,
        out, T, FUT, Btot);
}

// round 12
// speedup vs baseline: 2.3174x; 1.2119x over previous
#include <cuda_runtime.h>
#include <cuda_bf16.h>
#include <cstddef>
#include <cstdint>

// Two-layer LSTM recurrence, persistent kernel, TENSOR-CORE layer-1 GEMV.
// R12 = R11 with (a) the 3 split-precision passes FUSED into one kk-loop
// with operand reuse (Whi/hhi loaded once, not 2x), B via paired ldmatrix
// .x4, and (b) m-tiles split across warps: 20 compute warps, warp (g,mt)
// owns n-tiles 5g..5g+4 of one 16-row m-tile -> 5.25 warps/SMSP.
//
// 128 blocks x 672 threads:
//   warps 0-19 : compute. g = wid>>1 (n-group), mt = wid&1 (m-tile).
//   warp 20    : layer-2 (lane = batch elem), one step behind.

#define CELL     100
#define NB       32
#define THREADS  672
#define L2BASE   640
#define ASTRIDE  232      // bf16 per A row (hi 0-111, pad, lo 120-231); 464B
#define ALO      120      // col offset of h_lo region (16B aligned)
#define WSTR     120      // bf16 per W row; 240B
#define CSTRIDE  33       // c1sh row stride (floats)

#define LDSM_X4(r0,r1,r2,r3, addr) \
  asm volatile("ldmatrix.sync.aligned.m8n8.x4.shared.b16 {%0,%1,%2,%3}, [%4];" \
    : "=r"(r0), "=r"(r1), "=r"(r2), "=r"(r3) : "r"(addr))
#define LDSM_X2(r0,r1, addr) \
  asm volatile("ldmatrix.sync.aligned.m8n8.x2.shared.b16 {%0,%1}, [%2];" \
    : "=r"(r0), "=r"(r1) : "r"(addr))
#define MMA16816(d, a0,a1,a2,a3, b0,b1) \
  asm volatile("mma.sync.aligned.m16n8k16.row.col.f32.bf16.bf16.f32 " \
    "{%0,%1,%2,%3}, {%4,%5,%6,%7}, {%8,%9}, {%0,%1,%2,%3};" \
    : "+f"((d)[0]), "+f"((d)[1]), "+f"((d)[2]), "+f"((d)[3]) \
    : "r"(a0), "r"(a1), "r"(a2), "r"(a3), "r"(b0), "r"(b1))

__device__ __forceinline__ float rcp_approx(float x) {
    float r;
    asm("rcp.approx.f32 %0, %1;" : "=f"(r) : "f"(x));
    return r;
}
// ---- fast path (compute warps): single-MUFU HW tanh ----
__device__ __forceinline__ float tanh_hw(float x) {
    float r;
    asm("tanh.approx.f32 %0, %1;" : "=f"(r) : "f"(x));
    return r;
}
__device__ __forceinline__ float sigm_fast(float x) {
    return fmaf(0.5f, tanh_hw(0.5f * x), 0.5f);
}
// ---- exact path (layer-2 warp) ----
__device__ __forceinline__ float sigm(float x) {
    return rcp_approx(1.0f + __expf(-x));
}
__device__ __forceinline__ float tanh_f(float x) {
    float e = __expf(2.0f * x);
    return fmaf(-2.0f, rcp_approx(e + 1.0f), 1.0f);
}
__device__ __forceinline__ uint32_t smem_u32(const void* p) {
    return (uint32_t)__cvta_generic_to_shared(p);
}

__global__ void __launch_bounds__(THREADS, 1)
tsrnn_kernel(const float* __restrict__ input,
             const float* __restrict__ W_ih1, const float* __restrict__ W_hh1,
             const float* __restrict__ b_ih1, const float* __restrict__ b_hh1,
             const float* __restrict__ W_ih2, const float* __restrict__ W_hh2,
             const float* __restrict__ b_ih2, const float* __restrict__ b_hh2,
             float* __restrict__ out, int T, int FUT, int Btot)
{
    extern __shared__ char smem[];
    __nv_bfloat16* Whi = (__nv_bfloat16*)smem;          // [400][120] row n = 4u+k
    __nv_bfloat16* Wlo = Whi + 400 * WSTR;              // [400][120]
    __nv_bfloat16* Ash = Wlo + 400 * WSTR;              // [32][232]: hhi | pad | hlo
    float* c1sh   = (float*)(Ash + 32 * ASTRIDE);       // [100][33]
    float* w2i    = c1sh + CELL * CSTRIDE;              // [100][4]
    float* wih_sh = w2i + 400;                          // [100][4]
    float* bsum_sh= wih_sh + 400;                       // [100][4]
    float* xsh    = bsum_sh + 400;                      // [32] (future phase)

    const int tid    = threadIdx.x;
    const int bglob0 = blockIdx.x * NB;
    const int wid    = tid >> 5;
    const int lane   = tid & 31;

    // ================= staging =================
    for (int idx = tid; idx < 400 * 112; idx += THREADS) {
        int n = idx / 112, kk = idx - n * 112;
        int u = n >> 2, k = n & 3;
        float w = (kk < CELL) ? W_hh1[(k * CELL + u) * CELL + kk] : 0.0f;
        __nv_bfloat16 hi = __float2bfloat16(w);
        Whi[n * WSTR + kk] = hi;
        Wlo[n * WSTR + kk] = __float2bfloat16(w - __bfloat162float(hi));
    }
    for (int idx = tid; idx < 32 * ASTRIDE; idx += THREADS)
        Ash[idx] = __float2bfloat16(0.0f);
    for (int idx = tid; idx < CELL * CSTRIDE; idx += THREADS) c1sh[idx] = 0.0f;
    for (int idx = tid; idx < 400; idx += THREADS) {
        int u = idx >> 2, k = idx & 3;
        w2i[idx]    = W_ih2[k * CELL + u];
        wih_sh[idx] = W_ih1[k * CELL + u];
        bsum_sh[idx]= b_ih1[k * CELL + u] + b_hh1[k * CELL + u];
    }
    if (tid < NB) xsh[tid] = 0.0f;

    // ================= per-thread setup =================
    const bool cw = (wid < 20);                 // compute warp
    const bool l2 = (tid >= L2BASE);            // warp 20
    const int  g  = wid >> 1;                   // n-group (0..9)
    const int  mt = wid & 1;                    // m-tile (0..1)
    const int  q  = lane & 3;
    const int  pp = q & 1;                      // 0: holds (i,f); 1: holds (g,o)
    const int  rowbase = lane >> 2;
    const int  rowm = mt * 16 + rowbase + (pp ? 8 : 0);  // this thread's batch row

    // ldmatrix lane addresses (byte offsets precomputed)
    const uint32_t Au32  = smem_u32(Ash);
    const uint32_t Whi32 = smem_u32(Whi);
    const uint32_t WLO_OFF = (uint32_t)(400 * WSTR * 2); // Wlo - Whi in bytes
    uint32_t aaddr = 0, bp[2], bs4 = 0;
    if (cw) {
        // A: 16 rows of own m-tile, both k-halves
        aaddr = Au32 + ((mt * 16 + (lane & 15)) * ASTRIDE + (lane >> 4) * 8) * 2;
        // B pairs: x4 loads n-tiles (5g+2j, 5g+2j+1), both k-halves:
        //   lanes 0-7: (nt, k0) rows; 8-15: (nt, k1); 16-23: (nt+1, k0); 24-31: (nt+1, k1)
        const int sub = lane >> 3, l8 = lane & 7;
        const int ntoff = sub >> 1, khalf = sub & 1;
        #pragma unroll
        for (int j = 0; j < 2; j++) {
            int nt = 5 * g + 2 * j + ntoff;
            bp[j] = Whi32 + ((8 * nt + l8) * WSTR + khalf * 8) * 2;
        }
        // B single: n-tile 5g+4 (x2: lanes 0-15, two k-halves)
        const int l4 = lane & 15;
        bs4 = Whi32 + ((8 * (5 * g + 4) + (l4 & 7)) * WSTR + ((l4 >> 3) & 1) * 8) * 2;
    }

    // layer-2 per-lane constants + state
    const int bl2 = tid - L2BASE;
    float whh2[4], b2c[4];
    float h2 = 0.0f, c2 = 0.0f;
    if (l2) {
        #pragma unroll
        for (int k = 0; k < 4; k++) {
            whh2[k] = W_hh2[k];
            b2c[k]  = b_ih2[k] + b_hh2[k];
        }
    }

    float c1r[5];
    #pragma unroll
    for (int i = 0; i < 5; i++) c1r[i] = 0.0f;

    __syncthreads();

    // ================= main loop =================
    const int TOT = T + FUT;
    for (int t = 0; t < TOT; ++t) {
        const bool fut = (t >= T);
        float d[5][4];
        float xv = 0.0f;

        if (cw) {
            // ---- x prefetch (observed): LDG issued before the GEMM ----
            if (!fut) {
                xv = __ldg(input + (size_t)t * Btot + bglob0 + rowm);
            }

            // ---- phase 1: fused split-bf16 GEMM on h[t-1] ----
            // D = Ahi*Bhi + Alo*Bhi + Ahi*Blo, operands loaded ONCE per kk
            #pragma unroll
            for (int i = 0; i < 5; i++)
                #pragma unroll
                for (int r = 0; r < 4; r++) d[i][r] = 0.0f;

            #pragma unroll
            for (int kk = 0; kk < 7; kk++) {
                const uint32_t off = (uint32_t)(kk * 32);   // 16 cols * 2B

                uint32_t ah[4], al[4];
                LDSM_X4(ah[0], ah[1], ah[2], ah[3], aaddr + off);
                LDSM_X4(al[0], al[1], al[2], al[3], aaddr + ALO * 2 + off);

                #pragma unroll
                for (int j = 0; j < 2; j++) {
                    uint32_t bh0, bh1, bh2, bh3;
                    LDSM_X4(bh0, bh1, bh2, bh3, bp[j] + off);
                    MMA16816(d[2*j],   ah[0], ah[1], ah[2], ah[3], bh0, bh1);
                    MMA16816(d[2*j],   al[0], al[1], al[2], al[3], bh0, bh1);
                    MMA16816(d[2*j+1], ah[0], ah[1], ah[2], ah[3], bh2, bh3);
                    MMA16816(d[2*j+1], al[0], al[1], al[2], al[3], bh2, bh3);
                    uint32_t bl0, bl1, bl2r, bl3;
                    LDSM_X4(bl0, bl1, bl2r, bl3, bp[j] + off + WLO_OFF);
                    MMA16816(d[2*j],   ah[0], ah[1], ah[2], ah[3], bl0, bl1);
                    MMA16816(d[2*j+1], ah[0], ah[1], ah[2], ah[3], bl2r, bl3);
                }
                {
                    uint32_t b0, b1;
                    LDSM_X2(b0, b1, bs4 + off);
                    MMA16816(d[4], ah[0], ah[1], ah[2], ah[3], b0, b1);
                    MMA16816(d[4], al[0], al[1], al[2], al[3], b0, b1);
                    uint32_t c0, c1v;
                    LDSM_X2(c0, c1v, bs4 + off + WLO_OFF);
                    MMA16816(d[4], ah[0], ah[1], ah[2], ah[3], c0, c1v);
                }
            }
        } else if (l2) {
            // ---- layer-2 for step t-1 ----
            if (t > 0) {
                const int tt = t - 1;
                const float* cp = c1sh + bl2;
                float di = 0.f, df = 0.f, dg = 0.f, dz = 0.f;
                #pragma unroll 10
                for (int uu = 0; uu < CELL; uu++) {
                    float cv  = cp[uu * CSTRIDE];
                    float4 w4 = *(const float4*)(w2i + uu * 4);
                    di = fmaf(cv, w4.x, di);
                    df = fmaf(cv, w4.y, df);
                    dg = fmaf(cv, w4.z, dg);
                    dz = fmaf(cv, w4.w, dz);
                }
                float pi = fmaf(h2, whh2[0], di + b2c[0]);
                float pf = fmaf(h2, whh2[1], df + b2c[1]);
                float pg = fmaf(h2, whh2[2], dg + b2c[2]);
                float po = fmaf(h2, whh2[3], dz + b2c[3]);
                float c  = sigm(pf) * c2 + sigm(pi) * tanh_f(pg);
                c2 = c;
                h2 = sigm(po) * tanh_f(c);
                if (t >= T) xsh[bl2] = c;               // x for future step t
                if (tt >= T) out[(size_t)(bglob0 + bl2) * FUT + (tt - T)] = c;
            }
        }

        __syncthreads();   // D ready (regs); A/c1 reads done; xsh holds x(t)

        if (cw) {
            if (fut) xv = xsh[rowm];
            // ---- phase 2: epilogue (gates -> cell -> h split -> stores) ----
            #pragma unroll
            for (int i = 0; i < 5; i++) {
                const int u = 2 * (5 * g + i) + (q >> 1);
                float* dd = d[i];
                // exchange with lane^1: even keeps row r, odd keeps row r+8
                float g0 = pp ? dd[0] : dd[2];
                float g1 = pp ? dd[1] : dd[3];
                float r0 = __shfl_xor_sync(0xffffffffu, g0, 1);
                float r1 = __shfl_xor_sync(0xffffffffu, g1, 1);
                float gi, gf, gg, go;
                if (!pp) { gi = dd[0]; gf = dd[1]; gg = r0;    go = r1;    }
                else     { gi = r0;    gf = r1;    gg = dd[2]; go = dd[3]; }

                const float4 bs = *(const float4*)(bsum_sh + u * 4);
                const float4 wi = *(const float4*)(wih_sh + u * 4);
                float pi = fmaf(xv, wi.x, gi + bs.x);
                float pf = fmaf(xv, wi.y, gf + bs.y);
                float pg = fmaf(xv, wi.z, gg + bs.z);
                float po = fmaf(xv, wi.w, go + bs.w);
                float c = sigm_fast(pf) * c1r[i] + sigm_fast(pi) * tanh_hw(pg);
                c1r[i] = c;
                float h = sigm_fast(po) * tanh_hw(c);

                c1sh[u * CSTRIDE + rowm] = c;
                __nv_bfloat16 hh = __float2bfloat16(h);
                Ash[rowm * ASTRIDE + u]       = hh;
                Ash[rowm * ASTRIDE + ALO + u] =
                    __float2bfloat16(h - __bfloat162float(hh));
            }
        }

        __syncthreads();   // new A / c1 visible for next step
    }

    // drain: layer-2 for the final step TOT-1
    if (l2) {
        const int tt = TOT - 1;
        const float* cp = c1sh + bl2;
        float di = 0.f, df = 0.f, dg = 0.f, dz = 0.f;
        #pragma unroll 10
        for (int uu = 0; uu < CELL; uu++) {
            float cv  = cp[uu * CSTRIDE];
            float4 w4 = *(const float4*)(w2i + uu * 4);
            di = fmaf(cv, w4.x, di);
            df = fmaf(cv, w4.y, df);
            dg = fmaf(cv, w4.z, dg);
            dz = fmaf(cv, w4.w, dz);
        }
        float pi = fmaf(h2, whh2[0], di + b2c[0]);
        float pf = fmaf(h2, whh2[1], df + b2c[1]);
        float pg = fmaf(h2, whh2[2], dg + b2c[2]);
        float po = fmaf(h2, whh2[3], dz + b2c[3]);
        float c  = sigm(pf) * c2 + sigm(pi) * tanh_f(pg);
        out[(size_t)(bglob0 + bl2) * FUT + (tt - T)] = c;
    }
}

extern "C" void kernel_launch(void* const* d_in, const int* in_sizes, int n_in,
                              void* d_out, int out_size)
{
    const float* input = (const float*)d_in[0];
    const float* W_ih1 = (const float*)d_in[1];
    const float* W_hh1 = (const float*)d_in[2];
    const float* b_ih1 = (const float*)d_in[3];
    const float* b_hh1 = (const float*)d_in[4];
    const float* W_ih2 = (const float*)d_in[5];
    const float* W_hh2 = (const float*)d_in[6];
    const float* b_ih2 = (const float*)d_in[7];
    const float* b_hh2 = (const float*)d_in[8];
    float* out = (float*)d_out;

    const int Btot = 4096;
    const int T    = in_sizes[0] / Btot;   // 512
    const int FUT  = out_size   / Btot;    // 64

    const int smem = 400 * WSTR * 2 * 2      // Whi + Wlo      192,000 B
                   + 32 * ASTRIDE * 2        // Ash             14,848 B
                   + (CELL * CSTRIDE         // c1sh             3,300 f
                      + 400 + 400 + 400      // w2i, wih, bsum   1,200 f
                      + NB) * 4;             // xsh                 32 f
                                             // total ~224,976 B

    cudaFuncSetAttribute(tsrnn_kernel,
                         cudaFuncAttributeMaxDynamicSharedMemorySize, smem);

    tsrnn_kernel<<<Btot / NB, THREADS, smem>>>(
        input, W_ih1, W_hh1, b_ih1, b_hh1,
        W_ih2, W_hh2, b_ih2, b_hh2,
        out, T, FUT, Btot);
}